// round 2
// baseline (speedup 1.0000x reference)
#include <cuda_runtime.h>
#include <math.h>

#define N_B      32
#define HW       16384
#define N_BLK    4      // SPECTRUM+1 ansatz blocks
#define ANSATZ   2

__device__ __forceinline__ float2 cmul(float2 a, float2 b) {
    return make_float2(a.x * b.x - a.y * b.y, a.x * b.y + a.y * b.x);
}
__device__ __forceinline__ void cmadd(float2& acc, float2 a, float2 b) {
    acc.x += a.x * b.x - a.y * b.y;
    acc.y += a.x * b.y + a.y * b.x;
}

// ---------------------------------------------------------------------------
// Fused kernel. 64 blocks per batch, 256 threads each (grid = 2048).
// Threads 0..3 build this batch's 4 ansatz-block unitaries into shared,
// then every thread evaluates one element's 2-qubit circuit.
// ---------------------------------------------------------------------------
__global__ __launch_bounds__(256) void qlayer_fused(const float2* __restrict__ x,
                                                    const float* __restrict__ qs,
                                                    float* __restrict__ out) {
    __shared__ float2 sm[N_BLK * 16];  // 512 B: 4 matrices, row-major [r][c]

    int b = blockIdx.x >> 6;  // batch index
    int t = threadIdx.x;

    if (t < N_BLK) {
        int i = t;  // which ansatz block
        float2 M[4][4];
#pragma unroll
        for (int r = 0; r < 4; r++)
#pragma unroll
            for (int c = 0; c < 4; c++)
                M[r][c] = make_float2(r == c ? 1.0f : 0.0f, 0.0f);

#pragma unroll
        for (int j = 0; j < ANSATZ; j++) {
#pragma unroll
            for (int k = 0; k < 2; k++) {
                // qstyles layout: (32, 4, 2, 2, 3)
                const float* p = qs + ((((b * N_BLK + i) * ANSATZ + j) * 2 + k) * 3);
                float th = p[0], ph = p[1], lam = p[2];
                float ct, st, cl, sl, cp, sp;
                sincosf(0.5f * th, &st, &ct);
                sincosf(lam, &sl, &cl);
                sincosf(ph, &sp, &cp);
                // U3 = [[ct, -e^{i lam} st], [e^{i ph} st, e^{i(ph+lam)} ct]]
                float2 G00 = make_float2(ct, 0.0f);
                float2 G01 = make_float2(-cl * st, -sl * st);
                float2 G10 = make_float2(cp * st, sp * st);
                float2 G11 = make_float2((cp * cl - sp * sl) * ct,
                                         (cp * sl + sp * cl) * ct);
                // apply on wire k (wire0 = MSB): row pairs
                int r0a = (k == 0) ? 0 : 0;
                int r1a = (k == 0) ? 2 : 1;
                int r0b = (k == 0) ? 1 : 2;
                int r1b = (k == 0) ? 3 : 3;
#pragma unroll
                for (int c = 0; c < 4; c++) {
                    float2 a0 = M[r0a][c], a1 = M[r1a][c];
                    float2 n0 = cmul(G00, a0); cmadd(n0, G01, a1);
                    float2 n1 = cmul(G10, a0); cmadd(n1, G11, a1);
                    M[r0a][c] = n0; M[r1a][c] = n1;

                    float2 b0 = M[r0b][c], b1 = M[r1b][c];
                    float2 m0 = cmul(G00, b0); cmadd(m0, G01, b1);
                    float2 m1 = cmul(G10, b0); cmadd(m1, G11, b1);
                    M[r0b][c] = m0; M[r1b][c] = m1;
                }
            }
            // CNOT(ctrl=wire0, tgt=wire1): swap rows 2 and 3
#pragma unroll
            for (int c = 0; c < 4; c++) {
                float2 tmp = M[2][c]; M[2][c] = M[3][c]; M[3][c] = tmp;
            }
        }

        float2* dst = sm + i * 16;
#pragma unroll
        for (int r = 0; r < 4; r++)
#pragma unroll
            for (int c = 0; c < 4; c++)
                dst[r * 4 + c] = M[r][c];
    }
    __syncthreads();

    // ---- per-element circuit ----
    int e = blockIdx.x * 256 + t;  // global element index
    float2 xv = x[e];

    float a = 0.5f * (xv.x + xv.y);
    float d = 0.5f * (xv.x - xv.y);
    float sa, ca, sd, cd;
    __sincosf(a, &sa, &ca);
    __sincosf(d, &sd, &cd);
    float2 p0 = make_float2(ca, -sa);   // amp 00: e^{-ia}
    float2 p1 = make_float2(cd, -sd);   // amp 01: e^{-id}
    float2 p2 = make_float2(cd, sd);    // amp 10: e^{+id}
    float2 p3 = make_float2(ca, sa);    // amp 11: e^{+ia}

    // initial state = A0 |00> = column 0 of block-0 matrix
    float2 s0 = sm[0];
    float2 s1 = sm[4];
    float2 s2 = sm[8];
    float2 s3 = sm[12];

#pragma unroll
    for (int i = 1; i < N_BLK; i++) {
        float2 v0 = cmul(p0, s0);
        float2 v1 = cmul(p1, s1);
        float2 v2 = cmul(p2, s2);
        float2 v3 = cmul(p3, s3);
        const float2* A = sm + i * 16;
#pragma unroll
        for (int r = 0; r < 4; r++) {
            float2 acc = cmul(A[r * 4 + 0], v0);
            cmadd(acc, A[r * 4 + 1], v1);
            cmadd(acc, A[r * 4 + 2], v2);
            cmadd(acc, A[r * 4 + 3], v3);
            if (r == 0) s0 = acc;
            else if (r == 1) s1 = acc;
            else if (r == 2) s2 = acc;
            else s3 = acc;
        }
    }

    float ev = (s0.x * s0.x + s0.y * s0.y) + (s1.x * s1.x + s1.y * s1.y)
             - (s2.x * s2.x + s2.y * s2.y) - (s3.x * s3.x + s3.y * s3.y);
    out[e] = ev;
}

extern "C" void kernel_launch(void* const* d_in, const int* in_sizes, int n_in,
                              void* d_out, int out_size) {
    const float* x  = (const float*)d_in[0];   // (32, 16384, 2) f32
    const float* qs = (const float*)d_in[1];   // (32, 4, 2, 2, 3) f32
    float* out = (float*)d_out;                // (32, 16384) f32

    qlayer_fused<<<(N_B * HW) / 256, 256>>>((const float2*)x, qs, out);
}

// round 3
// speedup vs baseline: 1.1138x; 1.1138x over previous
#include <cuda_runtime.h>
#include <math.h>

#define N_B      32
#define HW       16384
#define N_BLK    4      // SPECTRUM+1 ansatz blocks

__device__ __forceinline__ float2 cmul(float2 a, float2 b) {
    return make_float2(a.x * b.x - a.y * b.y, a.x * b.y + a.y * b.x);
}
// conj(a) * b
__device__ __forceinline__ float2 cmulc(float2 a, float2 b) {
    return make_float2(a.x * b.x + a.y * b.y, a.x * b.y - a.y * b.x);
}
__device__ __forceinline__ void cmadd(float2& acc, float2 a, float2 b) {
    acc.x += a.x * b.x - a.y * b.y;
    acc.y += a.x * b.y + a.y * b.x;
}

struct SmemLayout {
    float2 sg[64];    // 16 U3 gates: [(i*4 + j*2 + k)*4 + (a*2+c)]
    float2 sM[4][16]; // 4 block unitaries, row-major
    float2 sH[16];    // H = M3^dag P M3
};

// Per-element circuit evaluation (matrices in shared, broadcast reads).
__device__ __forceinline__ float eval_elem(float x0, float x1, const SmemLayout* s) {
    float su, cu, sv, cv;
    __sincosf(x0, &su, &cu);
    __sincosf(x1, &sv, &cv);
    float2 u = make_float2(cu, su);   // e^{i x0}
    float2 v = make_float2(cv, sv);   // e^{i x1}
    float2 w = cmul(u, v);            // e^{i (x0+x1)}

    // initial state = column 0 of block-0 unitary
    float2 s0 = s->sM[0][0];
    float2 s1 = s->sM[0][4];
    float2 s2 = s->sM[0][8];
    float2 s3 = s->sM[0][12];

#pragma unroll
    for (int it = 1; it <= 2; it++) {
        // diagonal (global phase dropped): diag(1, v, u, uv)
        float2 v0 = s0;
        float2 v1 = cmul(v, s1);
        float2 v2 = cmul(u, s2);
        float2 v3 = cmul(w, s3);
        const float2* A = s->sM[it];
        float2 n0, n1, n2, n3;
        n0 = cmul(A[0], v0);  cmadd(n0, A[1], v1);  cmadd(n0, A[2], v2);  cmadd(n0, A[3], v3);
        n1 = cmul(A[4], v0);  cmadd(n1, A[5], v1);  cmadd(n1, A[6], v2);  cmadd(n1, A[7], v3);
        n2 = cmul(A[8], v0);  cmadd(n2, A[9], v1);  cmadd(n2, A[10], v2); cmadd(n2, A[11], v3);
        n3 = cmul(A[12], v0); cmadd(n3, A[13], v1); cmadd(n3, A[14], v2); cmadd(n3, A[15], v3);
        s0 = n0; s1 = n1; s2 = n2; s3 = n3;
    }

    // final diagonal
    float2 t0 = s0;
    float2 t1 = cmul(v, s1);
    float2 t2 = cmul(u, s2);
    float2 t3 = cmul(w, s3);

    // ev = t^dag H t   (H Hermitian; diag real)
    float ev = s->sH[0].x  * (t0.x * t0.x + t0.y * t0.y)
             + s->sH[5].x  * (t1.x * t1.x + t1.y * t1.y)
             + s->sH[10].x * (t2.x * t2.x + t2.y * t2.y)
             + s->sH[15].x * (t3.x * t3.x + t3.y * t3.y);
#pragma unroll
    for (int r = 0; r < 3; r++) {
#pragma unroll
        for (int c = r + 1; c < 4; c++) {
            float2 tr = (r == 0) ? t0 : (r == 1) ? t1 : t2;
            float2 tc = (c == 1) ? t1 : (c == 2) ? t2 : t3;
            float2 m = cmulc(tr, tc);            // conj(t_r) * t_c
            float2 h = s->sH[r * 4 + c];
            ev += 2.0f * (h.x * m.x - h.y * m.y); // 2 Re(H_rc * m)
        }
    }
    return ev;
}

// ---------------------------------------------------------------------------
// 1024 blocks (32 per batch), 256 threads; each thread does 2 elements.
// ---------------------------------------------------------------------------
__global__ __launch_bounds__(256, 4) void qlayer_fused(const float4* __restrict__ x,
                                                       const float* __restrict__ qs,
                                                       float2* __restrict__ out) {
    __shared__ SmemLayout s;

    int b = blockIdx.x >> 5;  // batch index (32 blocks per batch)
    int t = threadIdx.x;

    // ---- Stage 1: 16 threads build the sixteen 2x2 U3 gates ----
    if (t < 16) {
        int i = t >> 2;       // ansatz block 0..3
        int g = t & 3;        // gate (j,k): j = g>>1, k = g&1
        // qstyles layout: (32, 4, 2, 2, 3)
        const float* p = qs + (((b * N_BLK + i) * 4 + g) * 3);
        float th = p[0], ph = p[1], lam = p[2];
        float ct, st, cl, sl, cp, sp;
        __sincosf(0.5f * th, &st, &ct);
        __sincosf(lam, &sl, &cl);
        __sincosf(ph, &sp, &cp);
        float2* gd = s.sg + t * 4;
        gd[0] = make_float2(ct, 0.0f);                 // G[0][0]
        gd[1] = make_float2(-cl * st, -sl * st);       // G[0][1]
        gd[2] = make_float2(cp * st, sp * st);         // G[1][0]
        gd[3] = make_float2((cp * cl - sp * sl) * ct,  // G[1][1]
                            (cp * sl + sp * cl) * ct);
    }
    __syncthreads();

    // ---- Stage 2: 64 threads assemble M_i = C (U10 kron U11) C (U00 kron U01) ----
    if (t < 64) {
        int i = t >> 4;
        int rc = t & 15;
        int r = rc >> 2, c = rc & 3;
        const int sig[4] = {0, 1, 3, 2};  // CNOT row swap (amps 2<->3)
        const float2* g00 = s.sg + (i * 4 + 0) * 4;  // j=0, wire0
        const float2* g01 = s.sg + (i * 4 + 1) * 4;  // j=0, wire1
        const float2* g10 = s.sg + (i * 4 + 2) * 4;  // j=1, wire0
        const float2* g11 = s.sg + (i * 4 + 3) * 4;  // j=1, wire1
        int sr = sig[r];
        int a1 = sr >> 1, b1 = sr & 1;
        int cc = c >> 1, dc = c & 1;
        float2 acc = make_float2(0.0f, 0.0f);
#pragma unroll
        for (int m = 0; m < 4; m++) {
            int cm = m >> 1, dm = m & 1;
            int sm_ = sig[m];
            int am = sm_ >> 1, bm = sm_ & 1;
            // K1'[r][m] = U10[a1][cm] * U11[b1][dm]
            float2 k1 = cmul(g10[a1 * 2 + cm], g11[b1 * 2 + dm]);
            // K0'[m][c] = U00[am][cc] * U01[bm][dc]
            float2 k0 = cmul(g00[am * 2 + cc], g01[bm * 2 + dc]);
            cmadd(acc, k1, k0);
        }
        s.sM[i][r * 4 + c] = acc;
    }
    __syncthreads();

    // ---- Stage 3: 16 threads compute H = M3^dag P M3, P = diag(1,1,-1,-1) ----
    if (t < 16) {
        int r = t >> 2, c = t & 3;
        float2 acc = make_float2(0.0f, 0.0f);
#pragma unroll
        for (int m = 0; m < 4; m++) {
            float2 term = cmulc(s.sM[3][m * 4 + r], s.sM[3][m * 4 + c]);
            if (m >= 2) { term.x = -term.x; term.y = -term.y; }
            acc.x += term.x; acc.y += term.y;
        }
        s.sH[t] = acc;
    }
    __syncthreads();

    // ---- Main: each thread evaluates 2 elements ----
    int p = blockIdx.x * 256 + t;     // pair index
    float4 xv = x[p];                 // two elements: (x0,x1), (x0',x1')

    float ev0 = eval_elem(xv.x, xv.y, &s);
    float ev1 = eval_elem(xv.z, xv.w, &s);

    out[p] = make_float2(ev0, ev1);
}

extern "C" void kernel_launch(void* const* d_in, const int* in_sizes, int n_in,
                              void* d_out, int out_size) {
    const float* x  = (const float*)d_in[0];   // (32, 16384, 2) f32
    const float* qs = (const float*)d_in[1];   // (32, 4, 2, 2, 3) f32

    qlayer_fused<<<(N_B * HW) / 512, 256>>>((const float4*)x, qs, (float2*)d_out);
}

// round 4
// speedup vs baseline: 1.7456x; 1.5673x over previous
#include <cuda_runtime.h>
#include <math.h>

#define N_B      32
#define N_BLK    4      // SPECTRUM+1 ansatz blocks

// 25 Fourier coefficients per batch: [0]=c00 (real), [1..3]=2*c_{m,0} m=1..3,
// [4..24]=2*c_{m,n} for n=1..3, m=-3..3 (7 per n)
__device__ float2 g_coef[N_B * 25];

__device__ __forceinline__ float2 cmul(float2 a, float2 b) {
    return make_float2(a.x * b.x - a.y * b.y, a.x * b.y + a.y * b.x);
}
// conj(a) * b
__device__ __forceinline__ float2 cmulc(float2 a, float2 b) {
    return make_float2(a.x * b.x + a.y * b.y, a.x * b.y - a.y * b.x);
}
__device__ __forceinline__ void cmadd(float2& acc, float2 a, float2 b) {
    acc.x += a.x * b.x - a.y * b.y;
    acc.y += a.x * b.y + a.y * b.x;
}
// acc += a * conj(b)
__device__ __forceinline__ void cmadd_cj(float2& acc, float2 a, float2 b) {
    acc.x += a.x * b.x + a.y * b.y;
    acc.y += a.y * b.x - a.x * b.y;
}

// ---------------------------------------------------------------------------
// Kernel 1: per-batch Fourier coefficients. Grid = 32 blocks, 64 threads.
// ---------------------------------------------------------------------------
__global__ __launch_bounds__(64) void coef_kernel(const float* __restrict__ qs) {
    __shared__ float2 sg[64];     // 16 U3 gates
    __shared__ float2 sM[4][16];  // 4 block unitaries
    __shared__ float2 sS[4][16];  // amplitude spectra S[f][m0*4+m1]

    int b = blockIdx.x;
    int t = threadIdx.x;

    // Stage A: sixteen 2x2 U3 gates
    if (t < 16) {
        // qstyles layout: (32, 4, 2, 2, 3); g = j*2 + k
        const float* p = qs + ((b * 16 + t) * 3);
        float th = p[0], ph = p[1], lam = p[2];
        float ct, st, cl, sl, cp, sp;
        sincosf(0.5f * th, &st, &ct);
        sincosf(lam, &sl, &cl);
        sincosf(ph, &sp, &cp);
        float2* gd = sg + t * 4;
        gd[0] = make_float2(ct, 0.0f);
        gd[1] = make_float2(-cl * st, -sl * st);
        gd[2] = make_float2(cp * st, sp * st);
        gd[3] = make_float2((cp * cl - sp * sl) * ct, (cp * sl + sp * cl) * ct);
    }
    __syncthreads();

    // Stage B: M_i = C (U10 kron U11) C (U00 kron U01)
    {
        int i = t >> 4;
        int rc = t & 15;
        int r = rc >> 2, c = rc & 3;
        const int sig[4] = {0, 1, 3, 2};  // CNOT swaps amps 2<->3
        const float2* g00 = sg + (i * 4 + 0) * 4;
        const float2* g01 = sg + (i * 4 + 1) * 4;
        const float2* g10 = sg + (i * 4 + 2) * 4;
        const float2* g11 = sg + (i * 4 + 3) * 4;
        int sr = sig[r];
        int a1 = sr >> 1, b1 = sr & 1;
        int cc = c >> 1, dc = c & 1;
        float2 acc = make_float2(0.0f, 0.0f);
#pragma unroll
        for (int m = 0; m < 4; m++) {
            int cm = m >> 1, dm = m & 1;
            int sm_ = sig[m];
            int am = sm_ >> 1, bm = sm_ & 1;
            float2 k1 = cmul(g10[a1 * 2 + cm], g11[b1 * 2 + dm]);
            float2 k0 = cmul(g00[am * 2 + cc], g01[bm * 2 + dc]);
            cmadd(acc, k1, k0);
        }
        sM[i][r * 4 + c] = acc;
    }
    __syncthreads();

    // Init spectra: state = M0 column 0 at frequency (0,0)
    {
        int f = t >> 4, m = t & 15;
        sS[f][m] = (m == 0) ? sM[0][f * 4] : make_float2(0.0f, 0.0f);
    }
    __syncthreads();

    // 3 spectrum steps: S <- M_step * (freq-shift S)
    // shift: amp f (bits b0=f>>1 on x0, b1=f&1 on x1) gains e^{i(b0 x0 + b1 x1)}
    for (int step = 1; step <= 3; step++) {
        int g = t >> 4, m = t & 15;
        int m0 = m >> 2, m1 = m & 3;
        float2 val = make_float2(0.0f, 0.0f);
#pragma unroll
        for (int f = 0; f < 4; f++) {
            int b0 = f >> 1, b1 = f & 1;
            if (m0 >= b0 && m1 >= b1) {
                float2 src = sS[f][(m0 - b0) * 4 + (m1 - b1)];
                cmadd(val, sM[step][g * 4 + f], src);
            }
        }
        __syncthreads();
        sS[g][m] = val;
        __syncthreads();
    }

    // Stage E: c_{mn} = sum_f p_f sum_{a-b=(m,n)} S[f][a] conj(S[f][b])
    if (t < 25) {
        int m, n;
        if (t == 0)      { m = 0; n = 0; }
        else if (t < 4)  { m = t; n = 0; }
        else             { int idx = t - 4; n = idx / 7 + 1; m = idx % 7 - 3; }
        float2 acc = make_float2(0.0f, 0.0f);
#pragma unroll
        for (int f = 0; f < 4; f++) {
            float sgn = (f < 2) ? 1.0f : -1.0f;
            for (int a0 = 0; a0 < 4; a0++) {
                for (int a1 = 0; a1 < 4; a1++) {
                    int b0 = a0 - m, b1 = a1 - n;
                    if (b0 >= 0 && b0 < 4 && b1 >= 0 && b1 < 4) {
                        // S[a] * conj(S[b])
                        float2 p = cmulc(sS[f][b0 * 4 + b1], sS[f][a0 * 4 + a1]);
                        acc.x += sgn * p.x;
                        acc.y += sgn * p.y;
                    }
                }
            }
        }
        if (t > 0) { acc.x *= 2.0f; acc.y *= 2.0f; }  // fold the 2*Re factor
        g_coef[b * 25 + t] = acc;
    }
}

// ---------------------------------------------------------------------------
// Kernel 2: trig-poly evaluation. 1024 blocks x 128 threads, 4 elems/thread.
// ---------------------------------------------------------------------------
__device__ __forceinline__ float eval_poly(float x0, float x1, const float2* C) {
    float su, cu, sv, cv;
    __sincosf(x0, &su, &cu);
    __sincosf(x1, &sv, &cv);
    float2 u  = make_float2(cu, su);
    float2 v  = make_float2(cv, sv);
    float2 u2 = cmul(u, u);
    float2 u3 = cmul(u2, u);
    float2 v2 = cmul(v, v);
    float2 v3 = cmul(v2, v);

    // n = 0 terms (coefs pre-doubled): Re(c * u^m)
    float ev = C[0].x
             + (C[1].x * u.x  - C[1].y * u.y)
             + (C[2].x * u2.x - C[2].y * u2.y)
             + (C[3].x * u3.x - C[3].y * u3.y);

#pragma unroll
    for (int n = 1; n <= 3; n++) {
        const float2* Cn = C + 4 + (n - 1) * 7;  // m = -3..3
        float2 B = Cn[3];                         // m = 0
        cmadd(B, Cn[4], u);
        cmadd(B, Cn[5], u2);
        cmadd(B, Cn[6], u3);
        cmadd_cj(B, Cn[2], u);                    // m = -1: c * conj(u)
        cmadd_cj(B, Cn[1], u2);
        cmadd_cj(B, Cn[0], u3);
        float2 vn = (n == 1) ? v : (n == 2) ? v2 : v3;
        ev += B.x * vn.x - B.y * vn.y;            // Re(B * v^n)
    }
    return ev;
}

__global__ __launch_bounds__(128) void eval_kernel(const float4* __restrict__ x,
                                                   float2* __restrict__ out) {
    __shared__ float2 sC[25];
    int b = blockIdx.x >> 5;   // 32 blocks per batch
    int t = threadIdx.x;
    if (t < 25) sC[t] = g_coef[b * 25 + t];
    __syncthreads();

    int base = blockIdx.x * 256;   // float4 units per block
#pragma unroll
    for (int h = 0; h < 2; h++) {
        int idx = base + h * 128 + t;
        float4 xv = x[idx];                       // two (x0,x1) pairs
        float2 r;
        r.x = eval_poly(xv.x, xv.y, sC);
        r.y = eval_poly(xv.z, xv.w, sC);
        out[idx] = r;
    }
}

extern "C" void kernel_launch(void* const* d_in, const int* in_sizes, int n_in,
                              void* d_out, int out_size) {
    const float* x  = (const float*)d_in[0];   // (32, 16384, 2) f32
    const float* qs = (const float*)d_in[1];   // (32, 4, 2, 2, 3) f32

    coef_kernel<<<N_B, 64>>>(qs);
    eval_kernel<<<1024, 128>>>((const float4*)x, (float2*)d_out);
}

// round 5
// speedup vs baseline: 1.8540x; 1.0621x over previous
#include <cuda_runtime.h>
#include <math.h>

#define N_B      32
#define N_BLK    4

// Packed real coefficients, 56 floats (14 float4) per batch:
//  [0..7]  : n=0 : e0, ec1, es1, ec2, es2, ec3, es3, pad
//  then for n=1..3 (base = 8 + (n-1)*16):
//  [+0..7] : P_n : p0, pc1, ps1, pc2, ps2, pc3, ps3, pad
//  [+8..15]: Q_n : q0, qc1, qs1, qc2, qs2, qc3, qs3, pad
__device__ float4 g_coefR[N_B * 14];

__device__ __forceinline__ float2 cmul(float2 a, float2 b) {
    return make_float2(a.x * b.x - a.y * b.y, a.x * b.y + a.y * b.x);
}
__device__ __forceinline__ float2 cmulc(float2 a, float2 b) {  // conj(a)*b
    return make_float2(a.x * b.x + a.y * b.y, a.x * b.y - a.y * b.x);
}
__device__ __forceinline__ void cmadd(float2& acc, float2 a, float2 b) {
    acc.x += a.x * b.x - a.y * b.y;
    acc.y += a.x * b.y + a.y * b.x;
}

// ---------------------------------------------------------------------------
// Kernel 1: per-batch Fourier coefficients (complex), then real repack.
// Grid = 32 blocks, 64 threads.
// ---------------------------------------------------------------------------
__global__ __launch_bounds__(64) void coef_kernel(const float* __restrict__ qs) {
    __shared__ float2 sg[64];     // 16 U3 gates
    __shared__ float2 sM[4][16];  // 4 block unitaries
    __shared__ float2 sS[4][16];  // amplitude spectra S[f][m0*4+m1]
    __shared__ float2 cC[25];     // complex coefs (pre-doubled for t>0)

    int b = blockIdx.x;
    int t = threadIdx.x;

    // Stage A: sixteen 2x2 U3 gates
    if (t < 16) {
        const float* p = qs + ((b * 16 + t) * 3);  // (32,4,2,2,3)
        float th = p[0], ph = p[1], lam = p[2];
        float ct, st, cl, sl, cp, sp;
        __sincosf(0.5f * th, &st, &ct);
        __sincosf(lam, &sl, &cl);
        __sincosf(ph, &sp, &cp);
        float2* gd = sg + t * 4;
        gd[0] = make_float2(ct, 0.0f);
        gd[1] = make_float2(-cl * st, -sl * st);
        gd[2] = make_float2(cp * st, sp * st);
        gd[3] = make_float2((cp * cl - sp * sl) * ct, (cp * sl + sp * cl) * ct);
    }
    __syncthreads();

    // Stage B: M_i = C (U10 kron U11) C (U00 kron U01)
    {
        int i = t >> 4;
        int rc = t & 15;
        int r = rc >> 2, c = rc & 3;
        const int sig[4] = {0, 1, 3, 2};  // CNOT swaps amps 2<->3
        const float2* g00 = sg + (i * 4 + 0) * 4;
        const float2* g01 = sg + (i * 4 + 1) * 4;
        const float2* g10 = sg + (i * 4 + 2) * 4;
        const float2* g11 = sg + (i * 4 + 3) * 4;
        int sr = sig[r];
        int a1 = sr >> 1, b1 = sr & 1;
        int cc = c >> 1, dc = c & 1;
        float2 acc = make_float2(0.0f, 0.0f);
#pragma unroll
        for (int m = 0; m < 4; m++) {
            int cm = m >> 1, dm = m & 1;
            int sm_ = sig[m];
            int am = sm_ >> 1, bm = sm_ & 1;
            float2 k1 = cmul(g10[a1 * 2 + cm], g11[b1 * 2 + dm]);
            float2 k0 = cmul(g00[am * 2 + cc], g01[bm * 2 + dc]);
            cmadd(acc, k1, k0);
        }
        sM[i][r * 4 + c] = acc;
    }
    __syncthreads();

    // Init spectra: state = M0 column 0 at frequency (0,0)
    {
        int f = t >> 4, m = t & 15;
        sS[f][m] = (m == 0) ? sM[0][f * 4] : make_float2(0.0f, 0.0f);
    }
    __syncthreads();

    // 3 spectrum steps: S <- M_step * (freq-shift S)
    for (int step = 1; step <= 3; step++) {
        int g = t >> 4, m = t & 15;
        int m0 = m >> 2, m1 = m & 3;
        float2 val = make_float2(0.0f, 0.0f);
#pragma unroll
        for (int f = 0; f < 4; f++) {
            int b0 = f >> 1, b1 = f & 1;
            if (m0 >= b0 && m1 >= b1) {
                float2 src = sS[f][(m0 - b0) * 4 + (m1 - b1)];
                cmadd(val, sM[step][g * 4 + f], src);
            }
        }
        __syncthreads();
        sS[g][m] = val;
        __syncthreads();
    }

    // Stage E: complex coefs (autocorrelation with parity signs)
    if (t < 25) {
        int m, n;
        if (t == 0)      { m = 0; n = 0; }
        else if (t < 4)  { m = t; n = 0; }
        else             { int idx = t - 4; n = idx / 7 + 1; m = idx % 7 - 3; }
        float2 acc = make_float2(0.0f, 0.0f);
#pragma unroll
        for (int f = 0; f < 4; f++) {
            float sgn = (f < 2) ? 1.0f : -1.0f;
            for (int a0 = 0; a0 < 4; a0++) {
                for (int a1 = 0; a1 < 4; a1++) {
                    int b0 = a0 - m, b1 = a1 - n;
                    if (b0 >= 0 && b0 < 4 && b1 >= 0 && b1 < 4) {
                        float2 p = cmulc(sS[f][b0 * 4 + b1], sS[f][a0 * 4 + a1]);
                        acc.x += sgn * p.x;
                        acc.y += sgn * p.y;
                    }
                }
            }
        }
        if (t > 0) { acc.x *= 2.0f; acc.y *= 2.0f; }
        cC[t] = acc;
    }
    __syncthreads();

    // Stage F: repack into real basis, 56 floats
    if (t < 56) {
        float val = 0.0f;
        int j = t & 7;
        int grp = t >> 3;   // 0: n=0; 1/2: n=1 P/Q; 3/4: n=2; 5/6: n=3
        if (grp == 0) {
            if (j == 0) val = cC[0].x;
            else if (j < 7) {
                int m = (j + 1) >> 1;
                val = (j & 1) ? cC[m].x : -cC[m].y;
            }
        } else {
            int n = (grp + 1) >> 1;
            bool isQ = ((grp & 1) == 0);
            int cb = 4 + (n - 1) * 7 + 3;  // m=0 slot
            if (j == 0) val = isQ ? cC[cb].y : cC[cb].x;
            else if (j < 7) {
                int m = (j + 1) >> 1;
                bool isCos = (j & 1);
                float2 cp = cC[cb + m];
                float2 cm = cC[cb - m];
                if (!isQ) val = isCos ? (cp.x + cm.x) : (cm.y - cp.y);
                else      val = isCos ? (cp.y + cm.y) : (cp.x - cm.x);
            }
        }
        ((float*)g_coefR)[b * 56 + t] = val;
    }
}

// ---------------------------------------------------------------------------
// Kernel 2: real trig-poly evaluation.
// ---------------------------------------------------------------------------
__device__ __forceinline__ float eval_poly(float x0, float x1, const float4* C) {
    float c1, s1, d1, t1;
    __sincosf(x0, &s1, &c1);
    __sincosf(x1, &t1, &d1);
    float c2 = 2.0f * c1 * c1 - 1.0f, s2 = 2.0f * s1 * c1;
    float c3 = c2 * c1 - s2 * s1,     s3 = s2 * c1 + c2 * s1;
    float d2 = 2.0f * d1 * d1 - 1.0f, t2 = 2.0f * t1 * d1;
    float d3 = d2 * d1 - t2 * t1,     t3 = t2 * d1 + d2 * t1;

    float4 A = C[0], B = C[1];
    float E = A.x + A.y * c1 + A.z * s1 + A.w * c2
            + B.x * s2 + B.y * c3 + B.z * s3;

#pragma unroll
    for (int n = 1; n <= 3; n++) {
        float4 Pa = C[2 + (n - 1) * 4];
        float4 Pb = C[3 + (n - 1) * 4];
        float4 Qa = C[4 + (n - 1) * 4];
        float4 Qb = C[5 + (n - 1) * 4];
        float P = Pa.x + Pa.y * c1 + Pa.z * s1 + Pa.w * c2
                + Pb.x * s2 + Pb.y * c3 + Pb.z * s3;
        float Q = Qa.x + Qa.y * c1 + Qa.z * s1 + Qa.w * c2
                + Qb.x * s2 + Qb.y * c3 + Qb.z * s3;
        float dn = (n == 1) ? d1 : (n == 2) ? d2 : d3;
        float tn = (n == 1) ? t1 : (n == 2) ? t2 : t3;
        E += P * dn - Q * tn;
    }
    return E;
}

__global__ __launch_bounds__(256) void eval_kernel(const float4* __restrict__ x,
                                                   float2* __restrict__ out) {
    __shared__ float4 sC[14];
    int b = blockIdx.x >> 5;   // 32 blocks per batch
    int t = threadIdx.x;
    if (t < 14) sC[t] = g_coefR[b * 14 + t];
    __syncthreads();

    int idx = blockIdx.x * 256 + t;   // one float4 (2 elements) per thread
    float4 xv = x[idx];
    float2 r;
    r.x = eval_poly(xv.x, xv.y, sC);
    r.y = eval_poly(xv.z, xv.w, sC);
    out[idx] = r;
}

extern "C" void kernel_launch(void* const* d_in, const int* in_sizes, int n_in,
                              void* d_out, int out_size) {
    const float* x  = (const float*)d_in[0];   // (32, 16384, 2) f32
    const float* qs = (const float*)d_in[1];   // (32, 4, 2, 2, 3) f32

    coef_kernel<<<N_B, 64>>>(qs);
    eval_kernel<<<1024, 256>>>((const float4*)x, (float2*)d_out);
}